// round 9
// baseline (speedup 1.0000x reference)
#include <cuda_runtime.h>
#include <cuda_fp16.h>
#include <math.h>

#define N_NODES 100000
#define N_EDGES 1000000
#define SCAN_NB 98   // ceil(100000/1024)

// ---------------- scratch (static device globals; no allocation) ----------------
__device__ int    g_count[N_NODES];
__device__ int    g_off[N_NODES + 1];
__device__ int    g_cur[N_NODES];
__device__ int    g_bsum[128];
__device__ int    g_src_sorted[N_EDGES];
__device__ float  g_inv_deg[N_NODES];
__device__ __half g_xh [(size_t)N_NODES * 64];
__device__ __half g_agg[(size_t)N_NODES * 128];
__device__ __half g_h1 [(size_t)N_NODES * 128];
__device__ __half g_h2 [(size_t)N_NODES * 128];
__device__ __half g_t40h [(size_t)N_NODES * 40];  // layer3 cols 0..39 (agg operand, fp16)
__device__ float  g_troot[(size_t)N_NODES * 40];  // layer3 cols 40..79 (root path, fp32)
// pre-converted fp16 weights, k-contiguous per output column j: W[j][k]
__device__ __half g_wh1[128 * 128];
__device__ __half g_wh2[128 * 256];
__device__ __half g_wh3[80 * 128];

// ---------------- hist + x->fp16 convert + weight prep (fused) ----------------
__global__ void hist_conv_kernel(const int* __restrict__ dst,
                                 const float* __restrict__ x,
                                 const float* __restrict__ w1l, const float* __restrict__ w1r,
                                 const float* __restrict__ w2l, const float* __restrict__ w2r,
                                 const float* __restrict__ w3l, const float* __restrict__ w3r) {
    int i = blockIdx.x * blockDim.x + threadIdx.x;
    if (i < N_EDGES) atomicAdd(&g_count[dst[i]], 1);
    int base = i * 4;
    if (base < N_NODES * 64) {
        float4 v = *(const float4*)(x + base);
        __half2 p0 = __floats2half2_rn(v.x, v.y);
        __half2 p1 = __floats2half2_rn(v.z, v.w);
        uint2 pk;
        pk.x = *(unsigned*)&p0;
        pk.y = *(unsigned*)&p1;
        *(uint2*)(g_xh + base) = pk;
    }
    int p = i;
    if (p < 128 * 128) {
        int j = p >> 7, k = p & 127;
        float v = (k < 64) ? w1l[k * 128 + j] : w1r[(k - 64) * 128 + j];
        g_wh1[j * 128 + k] = __float2half_rn(v);
        return;
    }
    p -= 128 * 128;
    if (p >= 0 && p < 128 * 256) {
        int j = p >> 8, k = p & 255;
        float v = (k < 128) ? w2l[k * 128 + j] : w2r[(k - 128) * 128 + j];
        g_wh2[j * 256 + k] = __float2half_rn(v);
        return;
    }
    p -= 128 * 256;
    if (p >= 0 && p < 80 * 128) {
        int j = p >> 7, k = p & 127;
        float v = (j < 40) ? w3l[k * 40 + j] : w3r[k * 40 + (j - 40)];
        g_wh3[j * 128 + k] = __float2half_rn(v);
    }
}

// ---------------- 3-phase coalesced scan ----------------
__global__ void scanA_kernel() {
    __shared__ int s[1024];
    const int t = threadIdx.x;
    const int i = blockIdx.x * 1024 + t;
    int c = (i < N_NODES) ? g_count[i] : 0;
    s[t] = c;
    __syncthreads();
    for (int d = 1; d < 1024; d <<= 1) {
        int v = (t >= d) ? s[t - d] : 0;
        __syncthreads();
        s[t] += v;
        __syncthreads();
    }
    if (i < N_NODES) g_off[i] = s[t] - c;
    if (t == 1023) g_bsum[blockIdx.x] = s[1023];
}

__global__ void scanC_kernel() {
    __shared__ int bs[SCAN_NB];
    const int t = threadIdx.x;
    if (t < SCAN_NB) bs[t] = g_bsum[t];
    __syncthreads();
    if (t == 0) {
        int run = 0;
        for (int b = 0; b < SCAN_NB; b++) { int c = bs[b]; bs[b] = run; run += c; }
        if (blockIdx.x == 0) g_off[N_NODES] = run;
    }
    __syncthreads();
    int i = blockIdx.x * 1024 + t;
    if (i < N_NODES) {
        int off = g_off[i] + bs[blockIdx.x];
        int c = g_count[i];
        g_off[i] = off;
        g_cur[i] = off;
        g_inv_deg[i] = 1.0f / (float)(c > 1 ? c : 1);
        g_count[i] = 0;                         // re-zero for next graph replay
    }
}

__global__ void scatter_kernel(const int* __restrict__ src,
                               const int* __restrict__ dst) {
    int e = blockIdx.x * blockDim.x + threadIdx.x;
    if (e < N_EDGES) {
        int d = dst[e];
        int p = atomicAdd(&g_cur[d], 1);
        g_src_sorted[p] = src[e];
    }
}

// ---------------- deterministic neighbor order: warp bitonic sort ----------------
__global__ void sort_kernel() {
    int node = (blockIdx.x * blockDim.x + threadIdx.x) >> 5;
    int lane = threadIdx.x & 31;
    if (node >= N_NODES) return;
    int beg = g_off[node], end = g_off[node + 1];
    int deg = end - beg;
    if (deg <= 1) return;
    if (deg <= 32) {
        int v = (lane < deg) ? g_src_sorted[beg + lane] : 0x7FFFFFFF;
#pragma unroll
        for (int k = 2; k <= 32; k <<= 1) {
#pragma unroll
            for (int j = k >> 1; j; j >>= 1) {
                int o = __shfl_xor_sync(0xFFFFFFFFu, v, j);
                bool up    = ((lane & k) == 0);
                bool lower = ((lane & j) == 0);
                v = (up == lower) ? min(v, o) : max(v, o);
            }
        }
        if (lane < deg) g_src_sorted[beg + lane] = v;
    } else if (lane == 0) {
        for (int i = beg + 1; i < end; i++) {
            int key = g_src_sorted[i];
            int j = i - 1;
            while (j >= beg && g_src_sorted[j] > key) {
                g_src_sorted[j + 1] = g_src_sorted[j];
                j--;
            }
            g_src_sorted[j + 1] = key;
        }
    }
}

// ---------------- mean-agg, 64-wide: TWO nodes per warp (half-warp each) --------
__global__ void aggregate64_kernel(const __half* __restrict__ X,
                                   __half* __restrict__ OUT) {
    int gw   = (blockIdx.x * blockDim.x + threadIdx.x) >> 5;
    int lane = threadIdx.x & 31;
    int hw   = lane >> 4;
    int sl   = lane & 15;
    int node = gw * 2 + hw;
    if (node >= N_NODES) return;
    const int col = 4 * sl;
    int beg = g_off[node], end = g_off[node + 1];
    int deg = end - beg;
    int mx  = max(deg, __shfl_xor_sync(0xFFFFFFFFu, deg, 16));
    float a0 = 0.f, a1 = 0.f, a2 = 0.f, a3 = 0.f;
    for (int c = 0; c < mx; c += 16) {
        int m = deg - c; if (m > 16) m = 16;
        int sidx = (sl < m) ? __ldg(g_src_sorted + beg + c + sl) : 0;
        int mm = mx - c; if (mm > 16) mm = 16;
        for (int i = 0; i < mm; i += 4) {
            int s0 = __shfl_sync(0xFFFFFFFFu, sidx, i,     16);
            int s1 = __shfl_sync(0xFFFFFFFFu, sidx, i + 1, 16);
            int s2 = __shfl_sync(0xFFFFFFFFu, sidx, i + 2, 16);
            int s3 = __shfl_sync(0xFFFFFFFFu, sidx, i + 3, 16);
            float2 f;
            if (i < m) {
                uint2 v = *(const uint2*)(X + (size_t)s0 * 64 + col);
                f = __half22float2(*(__half2*)&v.x); a0 += f.x; a1 += f.y;
                f = __half22float2(*(__half2*)&v.y); a2 += f.x; a3 += f.y;
            }
            if (i + 1 < m) {
                uint2 v = *(const uint2*)(X + (size_t)s1 * 64 + col);
                f = __half22float2(*(__half2*)&v.x); a0 += f.x; a1 += f.y;
                f = __half22float2(*(__half2*)&v.y); a2 += f.x; a3 += f.y;
            }
            if (i + 2 < m) {
                uint2 v = *(const uint2*)(X + (size_t)s2 * 64 + col);
                f = __half22float2(*(__half2*)&v.x); a0 += f.x; a1 += f.y;
                f = __half22float2(*(__half2*)&v.y); a2 += f.x; a3 += f.y;
            }
            if (i + 3 < m) {
                uint2 v = *(const uint2*)(X + (size_t)s3 * 64 + col);
                f = __half22float2(*(__half2*)&v.x); a0 += f.x; a1 += f.y;
                f = __half22float2(*(__half2*)&v.y); a2 += f.x; a3 += f.y;
            }
        }
    }
    float inv = g_inv_deg[node];
    __half2 p0 = __floats2half2_rn(a0 * inv, a1 * inv);
    __half2 p1 = __floats2half2_rn(a2 * inv, a3 * inv);
    uint2 pk;
    pk.x = *(unsigned*)&p0;
    pk.y = *(unsigned*)&p1;
    *(uint2*)(OUT + (size_t)node * 64 + col) = pk;
}

// ---------------- mean-agg, 128-wide: one warp per node, MLP 8 -------------------
__global__ void aggregate128_kernel(const __half* __restrict__ X,
                                    __half* __restrict__ OUT) {
    int node = (blockIdx.x * blockDim.x + threadIdx.x) >> 5;
    int lane = threadIdx.x & 31;
    if (node >= N_NODES) return;
    const int col = 4 * lane;
    int beg = g_off[node], end = g_off[node + 1];
    float a0 = 0.f, a1 = 0.f, a2 = 0.f, a3 = 0.f;
    for (int c = beg; c < end; c += 32) {
        int m = end - c; if (m > 32) m = 32;
        int sidx = (lane < m) ? __ldg(g_src_sorted + c + lane) : 0;
        int i = 0;
        for (; i + 8 <= m; i += 8) {
            uint2 v[8];
#pragma unroll
            for (int u = 0; u < 8; u++) {
                int s = __shfl_sync(0xFFFFFFFFu, sidx, i + u);
                v[u] = *(const uint2*)(X + (size_t)s * 128 + col);
            }
#pragma unroll
            for (int u = 0; u < 8; u++) {
                float2 f;
                f = __half22float2(*(__half2*)&v[u].x); a0 += f.x; a1 += f.y;
                f = __half22float2(*(__half2*)&v[u].y); a2 += f.x; a3 += f.y;
            }
        }
        for (; i + 4 <= m; i += 4) {
            uint2 v[4];
#pragma unroll
            for (int u = 0; u < 4; u++) {
                int s = __shfl_sync(0xFFFFFFFFu, sidx, i + u);
                v[u] = *(const uint2*)(X + (size_t)s * 128 + col);
            }
#pragma unroll
            for (int u = 0; u < 4; u++) {
                float2 f;
                f = __half22float2(*(__half2*)&v[u].x); a0 += f.x; a1 += f.y;
                f = __half22float2(*(__half2*)&v[u].y); a2 += f.x; a3 += f.y;
            }
        }
        for (; i < m; i++) {
            int s = __shfl_sync(0xFFFFFFFFu, sidx, i);
            uint2 v0 = *(const uint2*)(X + (size_t)s * 128 + col);
            float2 f;
            f = __half22float2(*(__half2*)&v0.x); a0 += f.x; a1 += f.y;
            f = __half22float2(*(__half2*)&v0.y); a2 += f.x; a3 += f.y;
        }
    }
    float inv = g_inv_deg[node];
    __half2 p0 = __floats2half2_rn(a0 * inv, a1 * inv);
    __half2 p1 = __floats2half2_rn(a2 * inv, a3 * inv);
    uint2 pk;
    pk.x = *(unsigned*)&p0;
    pk.y = *(unsigned*)&p1;
    *(uint2*)(OUT + (size_t)node * 128 + col) = pk;
}

// ---------------- cp.async / ldmatrix / mma helpers ----------------
__device__ __forceinline__ void cp16(void* smem, const void* gmem, bool pred) {
    unsigned saddr = (unsigned)__cvta_generic_to_shared(smem);
    int sz = pred ? 16 : 0;
    asm volatile("cp.async.cg.shared.global [%0], [%1], 16, %2;\n"
                 :: "r"(saddr), "l"(gmem), "r"(sz));
}
__device__ __forceinline__ void cp_commit() {
    asm volatile("cp.async.commit_group;\n");
}
template <int NN>
__device__ __forceinline__ void cp_wait() {
    asm volatile("cp.async.wait_group %0;\n" :: "n"(NN));
}
__device__ __forceinline__ void ldsm_x4(unsigned* r, unsigned saddr) {
    asm volatile("ldmatrix.sync.aligned.m8n8.x4.shared.b16 {%0,%1,%2,%3}, [%4];\n"
                 : "=r"(r[0]), "=r"(r[1]), "=r"(r[2]), "=r"(r[3]) : "r"(saddr));
}
__device__ __forceinline__ void mma_f16(float* c, const unsigned* a, const unsigned* b) {
    asm volatile(
        "mma.sync.aligned.m16n8k16.row.col.f32.f16.f16.f32 "
        "{%0,%1,%2,%3}, {%4,%5,%6,%7}, {%8,%9}, {%0,%1,%2,%3};\n"
        : "+f"(c[0]), "+f"(c[1]), "+f"(c[2]), "+f"(c[3])
        : "r"(a[0]), "r"(a[1]), "r"(a[2]), "r"(a[3]),
          "r"(b[0]), "r"(b[1]));
}

// ---------------- cp.async + ldmatrix double-buffered fp16 GEMM ----------------
// C = [A1|A2] @ Wh^T + bias (optional relu).
// SPLIT40: cols 0..39 -> fp16 C40 [Nrows][40]; cols 40..79 -> fp32 Croot [Nrows][40].
template <int N, typename CT, bool SPLIT40>
__global__ void __launch_bounds__(256)
gemm_cp_kernel(const __half* __restrict__ A1, int K1,
               const __half* __restrict__ A2, int K2,
               const __half* __restrict__ Wh,
               const float* __restrict__ bias, int do_relu,
               CT* __restrict__ C, __half* __restrict__ C40,
               float* __restrict__ Croot, int Nrows) {
    constexpr int BM = 128, BK = 32, RS = 40;
    constexpr int NT = N / 8;
    constexpr int NP = NT / 2;
    constexpr int ABUF = BM * RS, WBUF = N * RS;
    __shared__ __align__(16) __half As[2][ABUF];
    __shared__ __align__(16) __half Ws[2][WBUF];

    const int tid  = threadIdx.x;
    const int warp = tid >> 5;
    const int lane = tid & 31;
    const int g  = lane >> 2;
    const int cq = lane & 3;
    const int rowBase = blockIdx.x * BM;
    const int Ktot = K1 + K2;
    const int T = Ktot / BK;

    const int lr = lane & 7;
    const unsigned aoff =
        (unsigned)(((warp * 16 + ((lane >> 3) & 1) * 8 + lr) * RS + ((lane >> 4) << 3)) * 2);
    const unsigned boff =
        (unsigned)(((((lane >> 4) << 3) + lr) * RS + (((lane >> 3) & 1) << 3)) * 2);
    const unsigned asBase = (unsigned)__cvta_generic_to_shared(&As[0][0]);
    const unsigned wsBase = (unsigned)__cvta_generic_to_shared(&Ws[0][0]);

    float acc[NT][4];
#pragma unroll
    for (int nt = 0; nt < NT; nt++)
#pragma unroll
        for (int i = 0; i < 4; i++) acc[nt][i] = 0.0f;

    auto issue = [&](int tt, int buf) {
        int kbase = tt * BK;
        const __half* A;
        int kloc, Kst;
        if (kbase < K1) { A = A1; kloc = kbase;      Kst = K1; }
        else            { A = A2; kloc = kbase - K1; Kst = K2; }
#pragma unroll
        for (int i = 0; i < 2; i++) {
            int c = tid + 256 * i;
            int row = c >> 2, part = c & 3;
            int grow = rowBase + row;
            const void* src = A + (size_t)grow * Kst + kloc + part * 8;
            cp16(&As[buf][row * RS + part * 8], src, grow < Nrows);
        }
        for (int c = tid; c < N * 4; c += 256) {
            int j = c >> 2, part = c & 3;
            const void* src = Wh + (size_t)j * Ktot + kbase + part * 8;
            cp16(&Ws[buf][j * RS + part * 8], src, true);
        }
    };

    issue(0, 0);
    cp_commit();
    for (int t = 0; t < T; t++) {
        const int buf = t & 1;
        if (t + 1 < T) { issue(t + 1, (t + 1) & 1); cp_commit(); cp_wait<1>(); }
        else           { cp_wait<0>(); }
        __syncthreads();
        const unsigned aB = asBase + (unsigned)(buf * ABUF * 2) + aoff;
        const unsigned wB = wsBase + (unsigned)(buf * WBUF * 2) + boff;
#pragma unroll
        for (int ks = 0; ks < BK; ks += 16) {
            unsigned a[4];
            ldsm_x4(a, aB + ks * 2);
#pragma unroll
            for (int np = 0; np < NP; np++) {
                unsigned b[4];
                ldsm_x4(b, wB + (unsigned)(np * 16 * RS * 2) + ks * 2);
                mma_f16(acc[2 * np],     a, b);
                mma_f16(acc[2 * np + 1], a, b + 2);
            }
        }
        __syncthreads();
    }

    const int row0 = rowBase + warp * 16 + g;
#pragma unroll
    for (int nt = 0; nt < NT; nt++) {
        int col = nt * 8 + 2 * cq;
        float v0 = acc[nt][0], v1 = acc[nt][1], v2 = acc[nt][2], v3 = acc[nt][3];
        if (bias) {
            float bc0 = bias[col], bc1 = bias[col + 1];
            v0 += bc0; v1 += bc1; v2 += bc0; v3 += bc1;
        }
        if (do_relu) {
            v0 = fmaxf(v0, 0.0f); v1 = fmaxf(v1, 0.0f);
            v2 = fmaxf(v2, 0.0f); v3 = fmaxf(v3, 0.0f);
        }
        if (SPLIT40) {
            if (col < 40) {
                if (row0 < Nrows) {
                    __half2 h = __floats2half2_rn(v0, v1);
                    *(unsigned*)(C40 + (size_t)row0 * 40 + col) = *(unsigned*)&h;
                }
                if (row0 + 8 < Nrows) {
                    __half2 h = __floats2half2_rn(v2, v3);
                    *(unsigned*)(C40 + (size_t)(row0 + 8) * 40 + col) = *(unsigned*)&h;
                }
            } else {
                int rc = col - 40;
                if (row0 < Nrows) {
                    float* p = Croot + (size_t)row0 * 40 + rc;
                    p[0] = v0; p[1] = v1;
                }
                if (row0 + 8 < Nrows) {
                    float* p = Croot + (size_t)(row0 + 8) * 40 + rc;
                    p[0] = v2; p[1] = v3;
                }
            }
        } else {
            if (row0 < Nrows) {
                CT* p = C + (size_t)row0 * N + col;
                if (sizeof(CT) == 2) {
                    __half2 h = __floats2half2_rn(v0, v1);
                    *(unsigned*)p = *(unsigned*)&h;
                } else {
                    ((float*)p)[0] = v0; ((float*)p)[1] = v1;
                }
            }
            if (row0 + 8 < Nrows) {
                CT* p = C + (size_t)(row0 + 8) * N + col;
                if (sizeof(CT) == 2) {
                    __half2 h = __floats2half2_rn(v2, v3);
                    *(unsigned*)p = *(unsigned*)&h;
                } else {
                    ((float*)p)[0] = v2; ((float*)p)[1] = v3;
                }
            }
        }
    }
}

// ---------------- fused: mean-agg of t40h (fp16) + root + bias + log_softmax ----
// 10 active lanes x 4 cols each; float4 epilogue.
__global__ void final_kernel(const float* __restrict__ b3,
                             float* __restrict__ out) {
    int node = (blockIdx.x * blockDim.x + threadIdx.x) >> 5;
    int lane = threadIdx.x & 31;
    if (node >= N_NODES) return;
    const bool act = (lane < 10);
    const int col = 4 * lane;
    int beg = g_off[node], end = g_off[node + 1];
    float a0 = 0.f, a1 = 0.f, a2 = 0.f, a3 = 0.f;
    for (int c = beg; c < end; c += 32) {
        int m = end - c; if (m > 32) m = 32;
        int sidx = (lane < m) ? __ldg(g_src_sorted + c + lane) : 0;
        int i = 0;
        for (; i + 8 <= m; i += 8) {
            uint2 v[8];
#pragma unroll
            for (int u = 0; u < 8; u++) {
                int s = __shfl_sync(0xFFFFFFFFu, sidx, i + u);
                if (act) v[u] = *(const uint2*)(g_t40h + (size_t)s * 40 + col);
            }
            if (act) {
#pragma unroll
                for (int u = 0; u < 8; u++) {
                    float2 f;
                    f = __half22float2(*(__half2*)&v[u].x); a0 += f.x; a1 += f.y;
                    f = __half22float2(*(__half2*)&v[u].y); a2 += f.x; a3 += f.y;
                }
            }
        }
        for (; i < m; i++) {
            int s = __shfl_sync(0xFFFFFFFFu, sidx, i);
            if (act) {
                uint2 v0 = *(const uint2*)(g_t40h + (size_t)s * 40 + col);
                float2 f;
                f = __half22float2(*(__half2*)&v0.x); a0 += f.x; a1 += f.y;
                f = __half22float2(*(__half2*)&v0.y); a2 += f.x; a3 += f.y;
            }
        }
    }
    float v0 = -INFINITY, v1 = -INFINITY, v2 = -INFINITY, v3 = -INFINITY;
    if (act) {
        float inv = g_inv_deg[node];
        float4 rt = *(const float4*)(g_troot + (size_t)node * 40 + col);
        float4 bb = *(const float4*)(b3 + col);
        v0 = a0 * inv + rt.x + bb.x;
        v1 = a1 * inv + rt.y + bb.y;
        v2 = a2 * inv + rt.z + bb.z;
        v3 = a3 * inv + rt.w + bb.w;
    }
    float m = fmaxf(fmaxf(v0, v1), fmaxf(v2, v3));
#pragma unroll
    for (int s = 16; s; s >>= 1) m = fmaxf(m, __shfl_xor_sync(0xFFFFFFFFu, m, s));
    float e = 0.0f;
    if (act)
        e = __expf(v0 - m) + __expf(v1 - m) + __expf(v2 - m) + __expf(v3 - m);
#pragma unroll
    for (int s = 16; s; s >>= 1) e += __shfl_xor_sync(0xFFFFFFFFu, e, s);
    float lse = m + logf(e);
    if (act) {
        float4 o;
        o.x = v0 - lse; o.y = v1 - lse; o.z = v2 - lse; o.w = v3 - lse;
        *(float4*)(out + (size_t)node * 40 + col) = o;
    }
}

// ---------------- launch ----------------
extern "C" void kernel_launch(void* const* d_in, const int* in_sizes, int n_in,
                              void* d_out, int out_size) {
    const float* x    = (const float*)d_in[0];
    const int*   ei   = (const int*)d_in[1];   // [2, E] int32: row0=src, row1=dst
    const float* w1_l = (const float*)d_in[2];
    const float* w1_r = (const float*)d_in[3];
    const float* b1   = (const float*)d_in[4];
    const float* w2_l = (const float*)d_in[5];
    const float* w2_r = (const float*)d_in[6];
    const float* b2   = (const float*)d_in[7];
    const float* w3_l = (const float*)d_in[8];
    const float* w3_r = (const float*)d_in[9];
    const float* b3   = (const float*)d_in[10];
    float* out = (float*)d_out;

    const int* src = ei;
    const int* dst = ei + N_EDGES;

    __half *xh, *agg, *h1, *h2, *wh1, *wh2, *wh3, *t40h;
    float *troot;
    cudaGetSymbolAddress((void**)&xh,    g_xh);
    cudaGetSymbolAddress((void**)&agg,   g_agg);
    cudaGetSymbolAddress((void**)&h1,    g_h1);
    cudaGetSymbolAddress((void**)&h2,    g_h2);
    cudaGetSymbolAddress((void**)&t40h,  g_t40h);
    cudaGetSymbolAddress((void**)&troot, g_troot);
    cudaGetSymbolAddress((void**)&wh1,   g_wh1);
    cudaGetSymbolAddress((void**)&wh2,   g_wh2);
    cudaGetSymbolAddress((void**)&wh3,   g_wh3);

    const int TB = 256;
    const int convThreads = (N_NODES * 64) / 4;                 // 1.6M
    const int histBlocks  = (convThreads + TB - 1) / TB;
    const int warpBlocks  = (N_NODES * 32 + TB - 1) / TB;
    const int pairBlocks  = (N_NODES / 2 * 32 + TB - 1) / TB;
    const int gemmBlocks  = (N_NODES + 127) / 128;

    // CSR build + x->fp16 + weight prep (g_count re-zeroed inside scanC)
    hist_conv_kernel<<<histBlocks, TB>>>(dst, x, w1_l, w1_r, w2_l, w2_r, w3_l, w3_r);
    scanA_kernel<<<SCAN_NB, 1024>>>();
    scanC_kernel<<<SCAN_NB, 1024>>>();
    scatter_kernel<<<(N_EDGES + TB - 1) / TB, TB>>>(src, dst);
    sort_kernel<<<warpBlocks, TB>>>();

    // Layer 1
    aggregate64_kernel<<<pairBlocks, TB>>>(xh, agg);
    gemm_cp_kernel<128, __half, false><<<gemmBlocks, TB>>>(
        agg, 64, xh, 64, wh1, b1, 1, h1, (half*)0, (float*)0, N_NODES);

    // Layer 2
    aggregate128_kernel<<<warpBlocks, TB>>>(h1, agg);
    gemm_cp_kernel<128, __half, false><<<gemmBlocks, TB>>>(
        agg, 128, h1, 128, wh2, b2, 1, h2, (half*)0, (float*)0, N_NODES);

    // Layer 3: split epilogue — t40h (fp16 agg operand) + troot (fp32 root path)
    gemm_cp_kernel<80, float, true><<<gemmBlocks, TB>>>(
        h2, 128, (const __half*)0, 0, wh3, (const float*)0, 0,
        (float*)0, t40h, troot, N_NODES);

    // fused: mean-agg of t40h + troot + b3 + log_softmax
    final_kernel<<<warpBlocks, TB>>>(b3, out);
}

// round 10
// speedup vs baseline: 1.0851x; 1.0851x over previous
#include <cuda_runtime.h>
#include <cuda_fp16.h>
#include <math.h>

#define N_NODES 100000
#define N_EDGES 1000000
#define SCAN_NB 98   // ceil(100000/1024)

// ---------------- scratch (static device globals; no allocation) ----------------
__device__ int    g_count[N_NODES];
__device__ int    g_off[N_NODES + 1];
__device__ int    g_cur[N_NODES];
__device__ int    g_bsum[128];
__device__ int    g_src_sorted[N_EDGES];
__device__ float  g_inv_deg[N_NODES];
__device__ __half g_xh [(size_t)N_NODES * 64];
__device__ __half g_agg[(size_t)N_NODES * 128];
__device__ __half g_h1 [(size_t)N_NODES * 128];
__device__ __half g_h2 [(size_t)N_NODES * 128];
__device__ __half g_t40h [(size_t)N_NODES * 40];  // layer3 cols 0..39 (agg operand, fp16)
__device__ float  g_troot[(size_t)N_NODES * 40];  // layer3 cols 40..79 (root path, fp32)
// pre-converted fp16 weights, k-contiguous per output column j: W[j][k]
__device__ __half g_wh1[128 * 128];
__device__ __half g_wh2[128 * 256];
__device__ __half g_wh3[80 * 128];

// ---------------- hist + x->fp16 convert + weight prep (fused) ----------------
__global__ void hist_conv_kernel(const int* __restrict__ dst,
                                 const float* __restrict__ x,
                                 const float* __restrict__ w1l, const float* __restrict__ w1r,
                                 const float* __restrict__ w2l, const float* __restrict__ w2r,
                                 const float* __restrict__ w3l, const float* __restrict__ w3r) {
    int i = blockIdx.x * blockDim.x + threadIdx.x;
    if (i < N_EDGES) atomicAdd(&g_count[dst[i]], 1);
    int base = i * 4;
    if (base < N_NODES * 64) {
        float4 v = *(const float4*)(x + base);
        __half2 p0 = __floats2half2_rn(v.x, v.y);
        __half2 p1 = __floats2half2_rn(v.z, v.w);
        uint2 pk;
        pk.x = *(unsigned*)&p0;
        pk.y = *(unsigned*)&p1;
        *(uint2*)(g_xh + base) = pk;
    }
    int p = i;
    if (p < 128 * 128) {
        int j = p >> 7, k = p & 127;
        float v = (k < 64) ? w1l[k * 128 + j] : w1r[(k - 64) * 128 + j];
        g_wh1[j * 128 + k] = __float2half_rn(v);
        return;
    }
    p -= 128 * 128;
    if (p >= 0 && p < 128 * 256) {
        int j = p >> 8, k = p & 255;
        float v = (k < 128) ? w2l[k * 128 + j] : w2r[(k - 128) * 128 + j];
        g_wh2[j * 256 + k] = __float2half_rn(v);
        return;
    }
    p -= 128 * 256;
    if (p >= 0 && p < 80 * 128) {
        int j = p >> 7, k = p & 127;
        float v = (j < 40) ? w3l[k * 40 + j] : w3r[k * 40 + (j - 40)];
        g_wh3[j * 128 + k] = __float2half_rn(v);
    }
}

// ---------------- 3-phase coalesced scan ----------------
__global__ void scanA_kernel() {
    __shared__ int s[1024];
    const int t = threadIdx.x;
    const int i = blockIdx.x * 1024 + t;
    int c = (i < N_NODES) ? g_count[i] : 0;
    s[t] = c;
    __syncthreads();
    for (int d = 1; d < 1024; d <<= 1) {
        int v = (t >= d) ? s[t - d] : 0;
        __syncthreads();
        s[t] += v;
        __syncthreads();
    }
    if (i < N_NODES) g_off[i] = s[t] - c;
    if (t == 1023) g_bsum[blockIdx.x] = s[1023];
}

__global__ void scanC_kernel() {
    __shared__ int bs[SCAN_NB];
    const int t = threadIdx.x;
    if (t < SCAN_NB) bs[t] = g_bsum[t];
    __syncthreads();
    if (t == 0) {
        int run = 0;
        for (int b = 0; b < SCAN_NB; b++) { int c = bs[b]; bs[b] = run; run += c; }
        if (blockIdx.x == 0) g_off[N_NODES] = run;
    }
    __syncthreads();
    int i = blockIdx.x * 1024 + t;
    if (i < N_NODES) {
        int off = g_off[i] + bs[blockIdx.x];
        int c = g_count[i];
        g_off[i] = off;
        g_cur[i] = off;
        g_inv_deg[i] = 1.0f / (float)(c > 1 ? c : 1);
        g_count[i] = 0;                         // re-zero for next graph replay
    }
}

__global__ void scatter_kernel(const int* __restrict__ src,
                               const int* __restrict__ dst) {
    int e = blockIdx.x * blockDim.x + threadIdx.x;
    if (e < N_EDGES) {
        int d = dst[e];
        int p = atomicAdd(&g_cur[d], 1);
        g_src_sorted[p] = src[e];
    }
}

// ---------------- deterministic neighbor order: warp bitonic sort ----------------
__global__ void sort_kernel() {
    int node = (blockIdx.x * blockDim.x + threadIdx.x) >> 5;
    int lane = threadIdx.x & 31;
    if (node >= N_NODES) return;
    int beg = g_off[node], end = g_off[node + 1];
    int deg = end - beg;
    if (deg <= 1) return;
    if (deg <= 32) {
        int v = (lane < deg) ? g_src_sorted[beg + lane] : 0x7FFFFFFF;
#pragma unroll
        for (int k = 2; k <= 32; k <<= 1) {
#pragma unroll
            for (int j = k >> 1; j; j >>= 1) {
                int o = __shfl_xor_sync(0xFFFFFFFFu, v, j);
                bool up    = ((lane & k) == 0);
                bool lower = ((lane & j) == 0);
                v = (up == lower) ? min(v, o) : max(v, o);
            }
        }
        if (lane < deg) g_src_sorted[beg + lane] = v;
    } else if (lane == 0) {
        for (int i = beg + 1; i < end; i++) {
            int key = g_src_sorted[i];
            int j = i - 1;
            while (j >= beg && g_src_sorted[j] > key) {
                g_src_sorted[j + 1] = g_src_sorted[j];
                j--;
            }
            g_src_sorted[j + 1] = key;
        }
    }
}

// ---------------- mean-agg, 64-wide: TWO nodes per warp (half-warp each) --------
__global__ void aggregate64_kernel(const __half* __restrict__ X,
                                   __half* __restrict__ OUT) {
    int gw   = (blockIdx.x * blockDim.x + threadIdx.x) >> 5;
    int lane = threadIdx.x & 31;
    int hw   = lane >> 4;
    int sl   = lane & 15;
    int node = gw * 2 + hw;
    if (node >= N_NODES) return;
    const int col = 4 * sl;
    int beg = g_off[node], end = g_off[node + 1];
    int deg = end - beg;
    int mx  = max(deg, __shfl_xor_sync(0xFFFFFFFFu, deg, 16));
    float a0 = 0.f, a1 = 0.f, a2 = 0.f, a3 = 0.f;
    for (int c = 0; c < mx; c += 16) {
        int m = deg - c; if (m > 16) m = 16;
        int sidx = (sl < m) ? __ldg(g_src_sorted + beg + c + sl) : 0;
        int mm = mx - c; if (mm > 16) mm = 16;
        for (int i = 0; i < mm; i += 4) {
            int s0 = __shfl_sync(0xFFFFFFFFu, sidx, i,     16);
            int s1 = __shfl_sync(0xFFFFFFFFu, sidx, i + 1, 16);
            int s2 = __shfl_sync(0xFFFFFFFFu, sidx, i + 2, 16);
            int s3 = __shfl_sync(0xFFFFFFFFu, sidx, i + 3, 16);
            float2 f;
            if (i < m) {
                uint2 v = *(const uint2*)(X + (size_t)s0 * 64 + col);
                f = __half22float2(*(__half2*)&v.x); a0 += f.x; a1 += f.y;
                f = __half22float2(*(__half2*)&v.y); a2 += f.x; a3 += f.y;
            }
            if (i + 1 < m) {
                uint2 v = *(const uint2*)(X + (size_t)s1 * 64 + col);
                f = __half22float2(*(__half2*)&v.x); a0 += f.x; a1 += f.y;
                f = __half22float2(*(__half2*)&v.y); a2 += f.x; a3 += f.y;
            }
            if (i + 2 < m) {
                uint2 v = *(const uint2*)(X + (size_t)s2 * 64 + col);
                f = __half22float2(*(__half2*)&v.x); a0 += f.x; a1 += f.y;
                f = __half22float2(*(__half2*)&v.y); a2 += f.x; a3 += f.y;
            }
            if (i + 3 < m) {
                uint2 v = *(const uint2*)(X + (size_t)s3 * 64 + col);
                f = __half22float2(*(__half2*)&v.x); a0 += f.x; a1 += f.y;
                f = __half22float2(*(__half2*)&v.y); a2 += f.x; a3 += f.y;
            }
        }
    }
    float inv = g_inv_deg[node];
    __half2 p0 = __floats2half2_rn(a0 * inv, a1 * inv);
    __half2 p1 = __floats2half2_rn(a2 * inv, a3 * inv);
    uint2 pk;
    pk.x = *(unsigned*)&p0;
    pk.y = *(unsigned*)&p1;
    *(uint2*)(OUT + (size_t)node * 64 + col) = pk;
}

// ---------------- mean-agg, 128-wide: one warp per node (MLP-4, R8 version) -----
__global__ void aggregate128_kernel(const __half* __restrict__ X,
                                    __half* __restrict__ OUT) {
    int node = (blockIdx.x * blockDim.x + threadIdx.x) >> 5;
    int lane = threadIdx.x & 31;
    if (node >= N_NODES) return;
    const int col = 4 * lane;
    int beg = g_off[node], end = g_off[node + 1];
    float a0 = 0.f, a1 = 0.f, a2 = 0.f, a3 = 0.f;
    for (int c = beg; c < end; c += 32) {
        int m = end - c; if (m > 32) m = 32;
        int sidx = (lane < m) ? __ldg(g_src_sorted + c + lane) : 0;
        int i = 0;
        for (; i + 4 <= m; i += 4) {
            int s0 = __shfl_sync(0xFFFFFFFFu, sidx, i);
            int s1 = __shfl_sync(0xFFFFFFFFu, sidx, i + 1);
            int s2 = __shfl_sync(0xFFFFFFFFu, sidx, i + 2);
            int s3 = __shfl_sync(0xFFFFFFFFu, sidx, i + 3);
            uint2 v0 = *(const uint2*)(X + (size_t)s0 * 128 + col);
            uint2 v1 = *(const uint2*)(X + (size_t)s1 * 128 + col);
            uint2 v2 = *(const uint2*)(X + (size_t)s2 * 128 + col);
            uint2 v3 = *(const uint2*)(X + (size_t)s3 * 128 + col);
            float2 f;
            f = __half22float2(*(__half2*)&v0.x); a0 += f.x; a1 += f.y;
            f = __half22float2(*(__half2*)&v0.y); a2 += f.x; a3 += f.y;
            f = __half22float2(*(__half2*)&v1.x); a0 += f.x; a1 += f.y;
            f = __half22float2(*(__half2*)&v1.y); a2 += f.x; a3 += f.y;
            f = __half22float2(*(__half2*)&v2.x); a0 += f.x; a1 += f.y;
            f = __half22float2(*(__half2*)&v2.y); a2 += f.x; a3 += f.y;
            f = __half22float2(*(__half2*)&v3.x); a0 += f.x; a1 += f.y;
            f = __half22float2(*(__half2*)&v3.y); a2 += f.x; a3 += f.y;
        }
        for (; i < m; i++) {
            int s0 = __shfl_sync(0xFFFFFFFFu, sidx, i);
            uint2 v0 = *(const uint2*)(X + (size_t)s0 * 128 + col);
            float2 f;
            f = __half22float2(*(__half2*)&v0.x); a0 += f.x; a1 += f.y;
            f = __half22float2(*(__half2*)&v0.y); a2 += f.x; a3 += f.y;
        }
    }
    float inv = g_inv_deg[node];
    __half2 p0 = __floats2half2_rn(a0 * inv, a1 * inv);
    __half2 p1 = __floats2half2_rn(a2 * inv, a3 * inv);
    uint2 pk;
    pk.x = *(unsigned*)&p0;
    pk.y = *(unsigned*)&p1;
    *(uint2*)(OUT + (size_t)node * 128 + col) = pk;
}

// ---------------- cp.async / ldmatrix / mma helpers ----------------
__device__ __forceinline__ void cp16(void* smem, const void* gmem, bool pred) {
    unsigned saddr = (unsigned)__cvta_generic_to_shared(smem);
    int sz = pred ? 16 : 0;
    asm volatile("cp.async.cg.shared.global [%0], [%1], 16, %2;\n"
                 :: "r"(saddr), "l"(gmem), "r"(sz));
}
__device__ __forceinline__ void cp_commit() {
    asm volatile("cp.async.commit_group;\n");
}
template <int NN>
__device__ __forceinline__ void cp_wait() {
    asm volatile("cp.async.wait_group %0;\n" :: "n"(NN));
}
__device__ __forceinline__ void ldsm_x4(unsigned* r, unsigned saddr) {
    asm volatile("ldmatrix.sync.aligned.m8n8.x4.shared.b16 {%0,%1,%2,%3}, [%4];\n"
                 : "=r"(r[0]), "=r"(r[1]), "=r"(r[2]), "=r"(r[3]) : "r"(saddr));
}
__device__ __forceinline__ void mma_f16(float* c, const unsigned* a, const unsigned* b) {
    asm volatile(
        "mma.sync.aligned.m16n8k16.row.col.f32.f16.f16.f32 "
        "{%0,%1,%2,%3}, {%4,%5,%6,%7}, {%8,%9}, {%0,%1,%2,%3};\n"
        : "+f"(c[0]), "+f"(c[1]), "+f"(c[2]), "+f"(c[3])
        : "r"(a[0]), "r"(a[1]), "r"(a[2]), "r"(a[3]),
          "r"(b[0]), "r"(b[1]));
}

// ---------------- cp.async + ldmatrix double-buffered fp16 GEMM ----------------
// C = [A1|A2] @ Wh^T + bias (optional relu).
// SPLIT40: cols 0..39 -> fp16 C40 [Nrows][40]; cols 40..79 -> fp32 Croot [Nrows][40].
template <int N, typename CT, bool SPLIT40>
__global__ void __launch_bounds__(256)
gemm_cp_kernel(const __half* __restrict__ A1, int K1,
               const __half* __restrict__ A2, int K2,
               const __half* __restrict__ Wh,
               const float* __restrict__ bias, int do_relu,
               CT* __restrict__ C, __half* __restrict__ C40,
               float* __restrict__ Croot, int Nrows) {
    constexpr int BM = 128, BK = 32, RS = 40;
    constexpr int NT = N / 8;
    constexpr int NP = NT / 2;
    constexpr int ABUF = BM * RS, WBUF = N * RS;
    __shared__ __align__(16) __half As[2][ABUF];
    __shared__ __align__(16) __half Ws[2][WBUF];

    const int tid  = threadIdx.x;
    const int warp = tid >> 5;
    const int lane = tid & 31;
    const int g  = lane >> 2;
    const int cq = lane & 3;
    const int rowBase = blockIdx.x * BM;
    const int Ktot = K1 + K2;
    const int T = Ktot / BK;

    const int lr = lane & 7;
    const unsigned aoff =
        (unsigned)(((warp * 16 + ((lane >> 3) & 1) * 8 + lr) * RS + ((lane >> 4) << 3)) * 2);
    const unsigned boff =
        (unsigned)(((((lane >> 4) << 3) + lr) * RS + (((lane >> 3) & 1) << 3)) * 2);
    const unsigned asBase = (unsigned)__cvta_generic_to_shared(&As[0][0]);
    const unsigned wsBase = (unsigned)__cvta_generic_to_shared(&Ws[0][0]);

    float acc[NT][4];
#pragma unroll
    for (int nt = 0; nt < NT; nt++)
#pragma unroll
        for (int i = 0; i < 4; i++) acc[nt][i] = 0.0f;

    auto issue = [&](int tt, int buf) {
        int kbase = tt * BK;
        const __half* A;
        int kloc, Kst;
        if (kbase < K1) { A = A1; kloc = kbase;      Kst = K1; }
        else            { A = A2; kloc = kbase - K1; Kst = K2; }
#pragma unroll
        for (int i = 0; i < 2; i++) {
            int c = tid + 256 * i;
            int row = c >> 2, part = c & 3;
            int grow = rowBase + row;
            const void* src = A + (size_t)grow * Kst + kloc + part * 8;
            cp16(&As[buf][row * RS + part * 8], src, grow < Nrows);
        }
        for (int c = tid; c < N * 4; c += 256) {
            int j = c >> 2, part = c & 3;
            const void* src = Wh + (size_t)j * Ktot + kbase + part * 8;
            cp16(&Ws[buf][j * RS + part * 8], src, true);
        }
    };

    issue(0, 0);
    cp_commit();
    for (int t = 0; t < T; t++) {
        const int buf = t & 1;
        if (t + 1 < T) { issue(t + 1, (t + 1) & 1); cp_commit(); cp_wait<1>(); }
        else           { cp_wait<0>(); }
        __syncthreads();
        const unsigned aB = asBase + (unsigned)(buf * ABUF * 2) + aoff;
        const unsigned wB = wsBase + (unsigned)(buf * WBUF * 2) + boff;
#pragma unroll
        for (int ks = 0; ks < BK; ks += 16) {
            unsigned a[4];
            ldsm_x4(a, aB + ks * 2);
#pragma unroll
            for (int np = 0; np < NP; np++) {
                unsigned b[4];
                ldsm_x4(b, wB + (unsigned)(np * 16 * RS * 2) + ks * 2);
                mma_f16(acc[2 * np],     a, b);
                mma_f16(acc[2 * np + 1], a, b + 2);
            }
        }
        __syncthreads();
    }

    const int row0 = rowBase + warp * 16 + g;
#pragma unroll
    for (int nt = 0; nt < NT; nt++) {
        int col = nt * 8 + 2 * cq;
        float v0 = acc[nt][0], v1 = acc[nt][1], v2 = acc[nt][2], v3 = acc[nt][3];
        if (bias) {
            float bc0 = bias[col], bc1 = bias[col + 1];
            v0 += bc0; v1 += bc1; v2 += bc0; v3 += bc1;
        }
        if (do_relu) {
            v0 = fmaxf(v0, 0.0f); v1 = fmaxf(v1, 0.0f);
            v2 = fmaxf(v2, 0.0f); v3 = fmaxf(v3, 0.0f);
        }
        if (SPLIT40) {
            if (col < 40) {
                if (row0 < Nrows) {
                    __half2 h = __floats2half2_rn(v0, v1);
                    *(unsigned*)(C40 + (size_t)row0 * 40 + col) = *(unsigned*)&h;
                }
                if (row0 + 8 < Nrows) {
                    __half2 h = __floats2half2_rn(v2, v3);
                    *(unsigned*)(C40 + (size_t)(row0 + 8) * 40 + col) = *(unsigned*)&h;
                }
            } else {
                int rc = col - 40;
                if (row0 < Nrows) {
                    float* p = Croot + (size_t)row0 * 40 + rc;
                    p[0] = v0; p[1] = v1;
                }
                if (row0 + 8 < Nrows) {
                    float* p = Croot + (size_t)(row0 + 8) * 40 + rc;
                    p[0] = v2; p[1] = v3;
                }
            }
        } else {
            if (row0 < Nrows) {
                CT* p = C + (size_t)row0 * N + col;
                if (sizeof(CT) == 2) {
                    __half2 h = __floats2half2_rn(v0, v1);
                    *(unsigned*)p = *(unsigned*)&h;
                } else {
                    ((float*)p)[0] = v0; ((float*)p)[1] = v1;
                }
            }
            if (row0 + 8 < Nrows) {
                CT* p = C + (size_t)(row0 + 8) * N + col;
                if (sizeof(CT) == 2) {
                    __half2 h = __floats2half2_rn(v2, v3);
                    *(unsigned*)p = *(unsigned*)&h;
                } else {
                    ((float*)p)[0] = v2; ((float*)p)[1] = v3;
                }
            }
        }
    }
}

// ---------------- fused: mean-agg of t40h (fp16) + root + bias + log_softmax ----
// 10 active lanes x 4 cols each; float4 epilogue; MLP-4 gather (R8-style).
__global__ void final_kernel(const float* __restrict__ b3,
                             float* __restrict__ out) {
    int node = (blockIdx.x * blockDim.x + threadIdx.x) >> 5;
    int lane = threadIdx.x & 31;
    if (node >= N_NODES) return;
    const bool act = (lane < 10);
    const int col = 4 * lane;
    int beg = g_off[node], end = g_off[node + 1];
    float a0 = 0.f, a1 = 0.f, a2 = 0.f, a3 = 0.f;
    for (int c = beg; c < end; c += 32) {
        int m = end - c; if (m > 32) m = 32;
        int sidx = (lane < m) ? __ldg(g_src_sorted + c + lane) : 0;
        int i = 0;
        for (; i + 4 <= m; i += 4) {
            int s0 = __shfl_sync(0xFFFFFFFFu, sidx, i);
            int s1 = __shfl_sync(0xFFFFFFFFu, sidx, i + 1);
            int s2 = __shfl_sync(0xFFFFFFFFu, sidx, i + 2);
            int s3 = __shfl_sync(0xFFFFFFFFu, sidx, i + 3);
            if (act) {
                uint2 v0 = *(const uint2*)(g_t40h + (size_t)s0 * 40 + col);
                uint2 v1 = *(const uint2*)(g_t40h + (size_t)s1 * 40 + col);
                uint2 v2 = *(const uint2*)(g_t40h + (size_t)s2 * 40 + col);
                uint2 v3 = *(const uint2*)(g_t40h + (size_t)s3 * 40 + col);
                float2 f;
                f = __half22float2(*(__half2*)&v0.x); a0 += f.x; a1 += f.y;
                f = __half22float2(*(__half2*)&v0.y); a2 += f.x; a3 += f.y;
                f = __half22float2(*(__half2*)&v1.x); a0 += f.x; a1 += f.y;
                f = __half22float2(*(__half2*)&v1.y); a2 += f.x; a3 += f.y;
                f = __half22float2(*(__half2*)&v2.x); a0 += f.x; a1 += f.y;
                f = __half22float2(*(__half2*)&v2.y); a2 += f.x; a3 += f.y;
                f = __half22float2(*(__half2*)&v3.x); a0 += f.x; a1 += f.y;
                f = __half22float2(*(__half2*)&v3.y); a2 += f.x; a3 += f.y;
            }
        }
        for (; i < m; i++) {
            int s0 = __shfl_sync(0xFFFFFFFFu, sidx, i);
            if (act) {
                uint2 v0 = *(const uint2*)(g_t40h + (size_t)s0 * 40 + col);
                float2 f;
                f = __half22float2(*(__half2*)&v0.x); a0 += f.x; a1 += f.y;
                f = __half22float2(*(__half2*)&v0.y); a2 += f.x; a3 += f.y;
            }
        }
    }
    float v0 = -INFINITY, v1 = -INFINITY, v2 = -INFINITY, v3 = -INFINITY;
    if (act) {
        float inv = g_inv_deg[node];
        float4 rt = *(const float4*)(g_troot + (size_t)node * 40 + col);
        float4 bb = *(const float4*)(b3 + col);
        v0 = a0 * inv + rt.x + bb.x;
        v1 = a1 * inv + rt.y + bb.y;
        v2 = a2 * inv + rt.z + bb.z;
        v3 = a3 * inv + rt.w + bb.w;
    }
    float m = fmaxf(fmaxf(v0, v1), fmaxf(v2, v3));
#pragma unroll
    for (int s = 16; s; s >>= 1) m = fmaxf(m, __shfl_xor_sync(0xFFFFFFFFu, m, s));
    float e = 0.0f;
    if (act)
        e = __expf(v0 - m) + __expf(v1 - m) + __expf(v2 - m) + __expf(v3 - m);
#pragma unroll
    for (int s = 16; s; s >>= 1) e += __shfl_xor_sync(0xFFFFFFFFu, e, s);
    float lse = m + logf(e);
    if (act) {
        float4 o;
        o.x = v0 - lse; o.y = v1 - lse; o.z = v2 - lse; o.w = v3 - lse;
        *(float4*)(out + (size_t)node * 40 + col) = o;
    }
}

// ---------------- launch ----------------
extern "C" void kernel_launch(void* const* d_in, const int* in_sizes, int n_in,
                              void* d_out, int out_size) {
    const float* x    = (const float*)d_in[0];
    const int*   ei   = (const int*)d_in[1];   // [2, E] int32: row0=src, row1=dst
    const float* w1_l = (const float*)d_in[2];
    const float* w1_r = (const float*)d_in[3];
    const float* b1   = (const float*)d_in[4];
    const float* w2_l = (const float*)d_in[5];
    const float* w2_r = (const float*)d_in[6];
    const float* b2   = (const float*)d_in[7];
    const float* w3_l = (const float*)d_in[8];
    const float* w3_r = (const float*)d_in[9];
    const float* b3   = (const float*)d_in[10];
    float* out = (float*)d_out;

    const int* src = ei;
    const int* dst = ei + N_EDGES;

    __half *xh, *agg, *h1, *h2, *wh1, *wh2, *wh3, *t40h;
    float *troot;
    cudaGetSymbolAddress((void**)&xh,    g_xh);
    cudaGetSymbolAddress((void**)&agg,   g_agg);
    cudaGetSymbolAddress((void**)&h1,    g_h1);
    cudaGetSymbolAddress((void**)&h2,    g_h2);
    cudaGetSymbolAddress((void**)&t40h,  g_t40h);
    cudaGetSymbolAddress((void**)&troot, g_troot);
    cudaGetSymbolAddress((void**)&wh1,   g_wh1);
    cudaGetSymbolAddress((void**)&wh2,   g_wh2);
    cudaGetSymbolAddress((void**)&wh3,   g_wh3);

    const int TB = 256;
    const int convThreads = (N_NODES * 64) / 4;                 // 1.6M
    const int histBlocks  = (convThreads + TB - 1) / TB;
    const int warpBlocks  = (N_NODES * 32 + TB - 1) / TB;
    const int pairBlocks  = (N_NODES / 2 * 32 + TB - 1) / TB;
    const int gemmBlocks  = (N_NODES + 127) / 128;

    // CSR build + x->fp16 + weight prep (g_count re-zeroed inside scanC)
    hist_conv_kernel<<<histBlocks, TB>>>(dst, x, w1_l, w1_r, w2_l, w2_r, w3_l, w3_r);
    scanA_kernel<<<SCAN_NB, 1024>>>();
    scanC_kernel<<<SCAN_NB, 1024>>>();
    scatter_kernel<<<(N_EDGES + TB - 1) / TB, TB>>>(src, dst);
    sort_kernel<<<warpBlocks, TB>>>();

    // Layer 1
    aggregate64_kernel<<<pairBlocks, TB>>>(xh, agg);
    gemm_cp_kernel<128, __half, false><<<gemmBlocks, TB>>>(
        agg, 64, xh, 64, wh1, b1, 1, h1, (half*)0, (float*)0, N_NODES);

    // Layer 2
    aggregate128_kernel<<<warpBlocks, TB>>>(h1, agg);
    gemm_cp_kernel<128, __half, false><<<gemmBlocks, TB>>>(
        agg, 128, h1, 128, wh2, b2, 1, h2, (half*)0, (float*)0, N_NODES);

    // Layer 3: split epilogue — t40h (fp16 agg operand) + troot (fp32 root path)
    gemm_cp_kernel<80, float, true><<<gemmBlocks, TB>>>(
        h2, 128, (const __half*)0, 0, wh3, (const float*)0, 0,
        (float*)0, t40h, troot, N_NODES);

    // fused: mean-agg of t40h + troot + b3 + log_softmax
    final_kernel<<<warpBlocks, TB>>>(b3, out);
}

// round 11
// speedup vs baseline: 1.2604x; 1.1616x over previous
#include <cuda_runtime.h>
#include <cuda_fp16.h>
#include <math.h>

#define N_NODES 100000
#define N_EDGES 1000000
#define SCAN_NB 98   // ceil(100000/1024)

// ---------------- scratch (static device globals; no allocation) ----------------
__device__ int    g_count[N_NODES];
__device__ int    g_off[N_NODES + 1];
__device__ int    g_cur[N_NODES];
__device__ int    g_bsum[128];
__device__ int    g_src_sorted[N_EDGES];
__device__ float  g_inv_deg[N_NODES];
__device__ __half g_xh [(size_t)N_NODES * 64];
__device__ __half g_agg[(size_t)N_NODES * 128];
__device__ __half g_h1 [(size_t)N_NODES * 128];
__device__ __half g_t40h [(size_t)N_NODES * 40];  // layer3 cols 0..39 (agg operand, fp16)
__device__ float  g_troot[(size_t)N_NODES * 40];  // layer3 cols 40..79 (root path, fp32)
// pre-converted fp16 weights, k-contiguous per output column j: W[j][k]
__device__ __half g_wh1[128 * 128];
__device__ __half g_wh2[128 * 256];
__device__ __half g_wh3[80 * 128];

// ---------------- hist + x->fp16 convert + weight prep (fused) ----------------
__global__ void hist_conv_kernel(const int* __restrict__ dst,
                                 const float* __restrict__ x,
                                 const float* __restrict__ w1l, const float* __restrict__ w1r,
                                 const float* __restrict__ w2l, const float* __restrict__ w2r,
                                 const float* __restrict__ w3l, const float* __restrict__ w3r) {
    int i = blockIdx.x * blockDim.x + threadIdx.x;
    if (i < N_EDGES) atomicAdd(&g_count[dst[i]], 1);
    int base = i * 4;
    if (base < N_NODES * 64) {
        float4 v = *(const float4*)(x + base);
        __half2 p0 = __floats2half2_rn(v.x, v.y);
        __half2 p1 = __floats2half2_rn(v.z, v.w);
        uint2 pk;
        pk.x = *(unsigned*)&p0;
        pk.y = *(unsigned*)&p1;
        *(uint2*)(g_xh + base) = pk;
    }
    int p = i;
    if (p < 128 * 128) {
        int j = p >> 7, k = p & 127;
        float v = (k < 64) ? w1l[k * 128 + j] : w1r[(k - 64) * 128 + j];
        g_wh1[j * 128 + k] = __float2half_rn(v);
        return;
    }
    p -= 128 * 128;
    if (p >= 0 && p < 128 * 256) {
        int j = p >> 8, k = p & 255;
        float v = (k < 128) ? w2l[k * 128 + j] : w2r[(k - 128) * 128 + j];
        g_wh2[j * 256 + k] = __float2half_rn(v);
        return;
    }
    p -= 128 * 256;
    if (p >= 0 && p < 80 * 128) {
        int j = p >> 7, k = p & 127;
        float v = (j < 40) ? w3l[k * 40 + j] : w3r[k * 40 + (j - 40)];
        g_wh3[j * 128 + k] = __float2half_rn(v);
    }
}

// ---------------- 3-phase coalesced scan ----------------
__global__ void scanA_kernel() {
    __shared__ int s[1024];
    const int t = threadIdx.x;
    const int i = blockIdx.x * 1024 + t;
    int c = (i < N_NODES) ? g_count[i] : 0;
    s[t] = c;
    __syncthreads();
    for (int d = 1; d < 1024; d <<= 1) {
        int v = (t >= d) ? s[t - d] : 0;
        __syncthreads();
        s[t] += v;
        __syncthreads();
    }
    if (i < N_NODES) g_off[i] = s[t] - c;
    if (t == 1023) g_bsum[blockIdx.x] = s[1023];
}

__global__ void scanC_kernel() {
    __shared__ int bs[SCAN_NB];
    const int t = threadIdx.x;
    if (t < SCAN_NB) bs[t] = g_bsum[t];
    __syncthreads();
    if (t == 0) {
        int run = 0;
        for (int b = 0; b < SCAN_NB; b++) { int c = bs[b]; bs[b] = run; run += c; }
        if (blockIdx.x == 0) g_off[N_NODES] = run;
    }
    __syncthreads();
    int i = blockIdx.x * 1024 + t;
    if (i < N_NODES) {
        int off = g_off[i] + bs[blockIdx.x];
        int c = g_count[i];
        g_off[i] = off;
        g_cur[i] = off;
        g_inv_deg[i] = 1.0f / (float)(c > 1 ? c : 1);
        g_count[i] = 0;                         // re-zero for next graph replay
    }
}

__global__ void scatter_kernel(const int* __restrict__ src,
                               const int* __restrict__ dst) {
    int e = blockIdx.x * blockDim.x + threadIdx.x;
    if (e < N_EDGES) {
        int d = dst[e];
        int p = atomicAdd(&g_cur[d], 1);
        g_src_sorted[p] = src[e];
    }
}

// ---------------- deterministic neighbor order: warp bitonic sort ----------------
__global__ void sort_kernel() {
    int node = (blockIdx.x * blockDim.x + threadIdx.x) >> 5;
    int lane = threadIdx.x & 31;
    if (node >= N_NODES) return;
    int beg = g_off[node], end = g_off[node + 1];
    int deg = end - beg;
    if (deg <= 1) return;
    if (deg <= 32) {
        int v = (lane < deg) ? g_src_sorted[beg + lane] : 0x7FFFFFFF;
#pragma unroll
        for (int k = 2; k <= 32; k <<= 1) {
#pragma unroll
            for (int j = k >> 1; j; j >>= 1) {
                int o = __shfl_xor_sync(0xFFFFFFFFu, v, j);
                bool up    = ((lane & k) == 0);
                bool lower = ((lane & j) == 0);
                v = (up == lower) ? min(v, o) : max(v, o);
            }
        }
        if (lane < deg) g_src_sorted[beg + lane] = v;
    } else if (lane == 0) {
        for (int i = beg + 1; i < end; i++) {
            int key = g_src_sorted[i];
            int j = i - 1;
            while (j >= beg && g_src_sorted[j] > key) {
                g_src_sorted[j + 1] = g_src_sorted[j];
                j--;
            }
            g_src_sorted[j + 1] = key;
        }
    }
}

// ---------------- mean-agg, 64-wide: TWO nodes per warp (half-warp each) --------
__global__ void aggregate64_kernel(const __half* __restrict__ X,
                                   __half* __restrict__ OUT) {
    int gw   = (blockIdx.x * blockDim.x + threadIdx.x) >> 5;
    int lane = threadIdx.x & 31;
    int hw   = lane >> 4;
    int sl   = lane & 15;
    int node = gw * 2 + hw;
    if (node >= N_NODES) return;
    const int col = 4 * sl;
    int beg = g_off[node], end = g_off[node + 1];
    int deg = end - beg;
    int mx  = max(deg, __shfl_xor_sync(0xFFFFFFFFu, deg, 16));
    float a0 = 0.f, a1 = 0.f, a2 = 0.f, a3 = 0.f;
    for (int c = 0; c < mx; c += 16) {
        int m = deg - c; if (m > 16) m = 16;
        int sidx = (sl < m) ? __ldg(g_src_sorted + beg + c + sl) : 0;
        int mm = mx - c; if (mm > 16) mm = 16;
        for (int i = 0; i < mm; i += 4) {
            int s0 = __shfl_sync(0xFFFFFFFFu, sidx, i,     16);
            int s1 = __shfl_sync(0xFFFFFFFFu, sidx, i + 1, 16);
            int s2 = __shfl_sync(0xFFFFFFFFu, sidx, i + 2, 16);
            int s3 = __shfl_sync(0xFFFFFFFFu, sidx, i + 3, 16);
            float2 f;
            if (i < m) {
                uint2 v = *(const uint2*)(X + (size_t)s0 * 64 + col);
                f = __half22float2(*(__half2*)&v.x); a0 += f.x; a1 += f.y;
                f = __half22float2(*(__half2*)&v.y); a2 += f.x; a3 += f.y;
            }
            if (i + 1 < m) {
                uint2 v = *(const uint2*)(X + (size_t)s1 * 64 + col);
                f = __half22float2(*(__half2*)&v.x); a0 += f.x; a1 += f.y;
                f = __half22float2(*(__half2*)&v.y); a2 += f.x; a3 += f.y;
            }
            if (i + 2 < m) {
                uint2 v = *(const uint2*)(X + (size_t)s2 * 64 + col);
                f = __half22float2(*(__half2*)&v.x); a0 += f.x; a1 += f.y;
                f = __half22float2(*(__half2*)&v.y); a2 += f.x; a3 += f.y;
            }
            if (i + 3 < m) {
                uint2 v = *(const uint2*)(X + (size_t)s3 * 64 + col);
                f = __half22float2(*(__half2*)&v.x); a0 += f.x; a1 += f.y;
                f = __half22float2(*(__half2*)&v.y); a2 += f.x; a3 += f.y;
            }
        }
    }
    float inv = g_inv_deg[node];
    __half2 p0 = __floats2half2_rn(a0 * inv, a1 * inv);
    __half2 p1 = __floats2half2_rn(a2 * inv, a3 * inv);
    uint2 pk;
    pk.x = *(unsigned*)&p0;
    pk.y = *(unsigned*)&p1;
    *(uint2*)(OUT + (size_t)node * 64 + col) = pk;
}

// ---------------- mean-agg, 128-wide: one warp per node (MLP-4) -----------------
__global__ void aggregate128_kernel(const __half* __restrict__ X,
                                    __half* __restrict__ OUT) {
    int node = (blockIdx.x * blockDim.x + threadIdx.x) >> 5;
    int lane = threadIdx.x & 31;
    if (node >= N_NODES) return;
    const int col = 4 * lane;
    int beg = g_off[node], end = g_off[node + 1];
    float a0 = 0.f, a1 = 0.f, a2 = 0.f, a3 = 0.f;
    for (int c = beg; c < end; c += 32) {
        int m = end - c; if (m > 32) m = 32;
        int sidx = (lane < m) ? __ldg(g_src_sorted + c + lane) : 0;
        int i = 0;
        for (; i + 4 <= m; i += 4) {
            int s0 = __shfl_sync(0xFFFFFFFFu, sidx, i);
            int s1 = __shfl_sync(0xFFFFFFFFu, sidx, i + 1);
            int s2 = __shfl_sync(0xFFFFFFFFu, sidx, i + 2);
            int s3 = __shfl_sync(0xFFFFFFFFu, sidx, i + 3);
            uint2 v0 = *(const uint2*)(X + (size_t)s0 * 128 + col);
            uint2 v1 = *(const uint2*)(X + (size_t)s1 * 128 + col);
            uint2 v2 = *(const uint2*)(X + (size_t)s2 * 128 + col);
            uint2 v3 = *(const uint2*)(X + (size_t)s3 * 128 + col);
            float2 f;
            f = __half22float2(*(__half2*)&v0.x); a0 += f.x; a1 += f.y;
            f = __half22float2(*(__half2*)&v0.y); a2 += f.x; a3 += f.y;
            f = __half22float2(*(__half2*)&v1.x); a0 += f.x; a1 += f.y;
            f = __half22float2(*(__half2*)&v1.y); a2 += f.x; a3 += f.y;
            f = __half22float2(*(__half2*)&v2.x); a0 += f.x; a1 += f.y;
            f = __half22float2(*(__half2*)&v2.y); a2 += f.x; a3 += f.y;
            f = __half22float2(*(__half2*)&v3.x); a0 += f.x; a1 += f.y;
            f = __half22float2(*(__half2*)&v3.y); a2 += f.x; a3 += f.y;
        }
        for (; i < m; i++) {
            int s0 = __shfl_sync(0xFFFFFFFFu, sidx, i);
            uint2 v0 = *(const uint2*)(X + (size_t)s0 * 128 + col);
            float2 f;
            f = __half22float2(*(__half2*)&v0.x); a0 += f.x; a1 += f.y;
            f = __half22float2(*(__half2*)&v0.y); a2 += f.x; a3 += f.y;
        }
    }
    float inv = g_inv_deg[node];
    __half2 p0 = __floats2half2_rn(a0 * inv, a1 * inv);
    __half2 p1 = __floats2half2_rn(a2 * inv, a3 * inv);
    uint2 pk;
    pk.x = *(unsigned*)&p0;
    pk.y = *(unsigned*)&p1;
    *(uint2*)(OUT + (size_t)node * 128 + col) = pk;
}

// ---------------- cp.async / ldmatrix / mma helpers ----------------
__device__ __forceinline__ void cp16(void* smem, const void* gmem, bool pred) {
    unsigned saddr = (unsigned)__cvta_generic_to_shared(smem);
    int sz = pred ? 16 : 0;
    asm volatile("cp.async.cg.shared.global [%0], [%1], 16, %2;\n"
                 :: "r"(saddr), "l"(gmem), "r"(sz));
}
__device__ __forceinline__ void cp_commit() {
    asm volatile("cp.async.commit_group;\n");
}
template <int NN>
__device__ __forceinline__ void cp_wait() {
    asm volatile("cp.async.wait_group %0;\n" :: "n"(NN));
}
__device__ __forceinline__ void ldsm_x4(unsigned* r, unsigned saddr) {
    asm volatile("ldmatrix.sync.aligned.m8n8.x4.shared.b16 {%0,%1,%2,%3}, [%4];\n"
                 : "=r"(r[0]), "=r"(r[1]), "=r"(r[2]), "=r"(r[3]) : "r"(saddr));
}
__device__ __forceinline__ void mma_f16(float* c, const unsigned* a, const unsigned* b) {
    asm volatile(
        "mma.sync.aligned.m16n8k16.row.col.f32.f16.f16.f32 "
        "{%0,%1,%2,%3}, {%4,%5,%6,%7}, {%8,%9}, {%0,%1,%2,%3};\n"
        : "+f"(c[0]), "+f"(c[1]), "+f"(c[2]), "+f"(c[3])
        : "r"(a[0]), "r"(a[1]), "r"(a[2]), "r"(a[3]),
          "r"(b[0]), "r"(b[1]));
}

// ---------------- layer-1 GEMM: h1 = relu([agg|xh] @ wh1^T + b1) ----------------
// BM=128, BK=32, RS=40; cp.async double-buffered; ldmatrix mainloop.
__global__ void __launch_bounds__(256)
gemm1_kernel(const __half* __restrict__ A1, int K1,
             const __half* __restrict__ A2, int K2,
             const __half* __restrict__ Wh,
             const float* __restrict__ bias,
             __half* __restrict__ C, int Nrows) {
    constexpr int N = 128, BM = 128, BK = 32, RS = 40;
    constexpr int NT = N / 8, NP = NT / 2;
    constexpr int ABUF = BM * RS, WBUF = N * RS;
    __shared__ __align__(16) __half As[2][ABUF];
    __shared__ __align__(16) __half Ws[2][WBUF];

    const int tid  = threadIdx.x;
    const int warp = tid >> 5;
    const int lane = tid & 31;
    const int g  = lane >> 2;
    const int cq = lane & 3;
    const int rowBase = blockIdx.x * BM;
    const int Ktot = K1 + K2;
    const int T = Ktot / BK;

    const int lr = lane & 7;
    const unsigned aoff =
        (unsigned)(((warp * 16 + ((lane >> 3) & 1) * 8 + lr) * RS + ((lane >> 4) << 3)) * 2);
    const unsigned boff =
        (unsigned)(((((lane >> 4) << 3) + lr) * RS + (((lane >> 3) & 1) << 3)) * 2);
    const unsigned asBase = (unsigned)__cvta_generic_to_shared(&As[0][0]);
    const unsigned wsBase = (unsigned)__cvta_generic_to_shared(&Ws[0][0]);

    float acc[NT][4];
#pragma unroll
    for (int nt = 0; nt < NT; nt++)
#pragma unroll
        for (int i = 0; i < 4; i++) acc[nt][i] = 0.0f;

    auto issue = [&](int tt, int buf) {
        int kbase = tt * BK;
        const __half* A;
        int kloc, Kst;
        if (kbase < K1) { A = A1; kloc = kbase;      Kst = K1; }
        else            { A = A2; kloc = kbase - K1; Kst = K2; }
#pragma unroll
        for (int i = 0; i < 2; i++) {
            int c = tid + 256 * i;
            int row = c >> 2, part = c & 3;
            int grow = rowBase + row;
            const void* src = A + (size_t)grow * Kst + kloc + part * 8;
            cp16(&As[buf][row * RS + part * 8], src, grow < Nrows);
        }
        for (int c = tid; c < N * 4; c += 256) {
            int j = c >> 2, part = c & 3;
            const void* src = Wh + (size_t)j * Ktot + kbase + part * 8;
            cp16(&Ws[buf][j * RS + part * 8], src, true);
        }
    };

    issue(0, 0);
    cp_commit();
    for (int t = 0; t < T; t++) {
        const int buf = t & 1;
        if (t + 1 < T) { issue(t + 1, (t + 1) & 1); cp_commit(); cp_wait<1>(); }
        else           { cp_wait<0>(); }
        __syncthreads();
        const unsigned aB = asBase + (unsigned)(buf * ABUF * 2) + aoff;
        const unsigned wB = wsBase + (unsigned)(buf * WBUF * 2) + boff;
#pragma unroll
        for (int ks = 0; ks < BK; ks += 16) {
            unsigned a[4];
            ldsm_x4(a, aB + ks * 2);
#pragma unroll
            for (int np = 0; np < NP; np++) {
                unsigned b[4];
                ldsm_x4(b, wB + (unsigned)(np * 16 * RS * 2) + ks * 2);
                mma_f16(acc[2 * np],     a, b);
                mma_f16(acc[2 * np + 1], a, b + 2);
            }
        }
        __syncthreads();
    }

    const int row0 = rowBase + warp * 16 + g;
#pragma unroll
    for (int nt = 0; nt < NT; nt++) {
        int col = nt * 8 + 2 * cq;
        float v0 = acc[nt][0] + bias[col], v1 = acc[nt][1] + bias[col + 1];
        float v2 = acc[nt][2] + bias[col], v3 = acc[nt][3] + bias[col + 1];
        v0 = fmaxf(v0, 0.0f); v1 = fmaxf(v1, 0.0f);
        v2 = fmaxf(v2, 0.0f); v3 = fmaxf(v3, 0.0f);
        if (row0 < Nrows) {
            __half2 h = __floats2half2_rn(v0, v1);
            *(unsigned*)(C + (size_t)row0 * N + col) = *(unsigned*)&h;
        }
        if (row0 + 8 < Nrows) {
            __half2 h = __floats2half2_rn(v2, v3);
            *(unsigned*)(C + (size_t)(row0 + 8) * N + col) = *(unsigned*)&h;
        }
    }
}

// ---------------- fused layer-2 + layer-3 GEMM ----------------
// Phase 1: acc = [agg|h1] @ wh2^T (K=256), bias2+relu -> h2 tile in SMEM (fp16).
// Phase 2: t = h2_tile @ wh3^T (K=128, N=80) -> split epilogue t40h/troot.
// Dynamic SMEM layout (halves): [0, 20480) = phase-1 As/Ws double buffers;
// overlay after phase 1: H = [0, 17408) (128 x RS2=136), W3 = [17408, 28288).
#define GEMM23_SMEM_HALVES 28288
__global__ void __launch_bounds__(256)
gemm23_kernel(const __half* __restrict__ A1,   // agg, K=128
              const __half* __restrict__ A2,   // h1,  K=128
              const __half* __restrict__ Wh2,  // [128][256]
              const __half* __restrict__ Wh3,  // [80][128]
              const float* __restrict__ bias2,
              __half* __restrict__ C40, float* __restrict__ Croot, int Nrows) {
    constexpr int N = 128, BM = 128, BK = 32, RS = 40, RS2 = 136;
    constexpr int NT = N / 8, NP = NT / 2;
    constexpr int ABUF = BM * RS, WBUF = N * RS;
    extern __shared__ __align__(16) __half sm[];
    __half* As = sm;                  // 2 x ABUF
    __half* Ws = sm + 2 * ABUF;       // 2 x WBUF
    __half* H  = sm;                  // 128 x RS2 (overlay, used after phase 1)
    __half* W3 = sm + 128 * RS2;      // 80 x RS2

    const int tid  = threadIdx.x;
    const int warp = tid >> 5;
    const int lane = tid & 31;
    const int g  = lane >> 2;
    const int cq = lane & 3;
    const int rowBase = blockIdx.x * BM;
    const int K1 = 128, Ktot = 256;
    const int T = Ktot / BK;

    const int lr = lane & 7;
    const unsigned aoff =
        (unsigned)(((warp * 16 + ((lane >> 3) & 1) * 8 + lr) * RS + ((lane >> 4) << 3)) * 2);
    const unsigned boff =
        (unsigned)(((((lane >> 4) << 3) + lr) * RS + (((lane >> 3) & 1) << 3)) * 2);
    const unsigned asBase = (unsigned)__cvta_generic_to_shared(As);
    const unsigned wsBase = (unsigned)__cvta_generic_to_shared(Ws);

    float acc[NT][4];
#pragma unroll
    for (int nt = 0; nt < NT; nt++)
#pragma unroll
        for (int i = 0; i < 4; i++) acc[nt][i] = 0.0f;

    auto issue = [&](int tt, int buf) {
        int kbase = tt * BK;
        const __half* A = (kbase < K1) ? A1 : A2;
        int kloc = (kbase < K1) ? kbase : kbase - K1;
#pragma unroll
        for (int i = 0; i < 2; i++) {
            int c = tid + 256 * i;
            int row = c >> 2, part = c & 3;
            int grow = rowBase + row;
            const void* src = A + (size_t)grow * 128 + kloc + part * 8;
            cp16(&As[buf * ABUF + row * RS + part * 8], src, grow < Nrows);
        }
        for (int c = tid; c < N * 4; c += 256) {
            int j = c >> 2, part = c & 3;
            const void* src = Wh2 + (size_t)j * Ktot + kbase + part * 8;
            cp16(&Ws[buf * WBUF + j * RS + part * 8], src, true);
        }
    };

    issue(0, 0);
    cp_commit();
    for (int t = 0; t < T; t++) {
        const int buf = t & 1;
        if (t + 1 < T) { issue(t + 1, (t + 1) & 1); cp_commit(); cp_wait<1>(); }
        else           { cp_wait<0>(); }
        __syncthreads();
        const unsigned aB = asBase + (unsigned)(buf * ABUF * 2) + aoff;
        const unsigned wB = wsBase + (unsigned)(buf * WBUF * 2) + boff;
#pragma unroll
        for (int ks = 0; ks < BK; ks += 16) {
            unsigned a[4];
            ldsm_x4(a, aB + ks * 2);
#pragma unroll
            for (int np = 0; np < NP; np++) {
                unsigned b[4];
                ldsm_x4(b, wB + (unsigned)(np * 16 * RS * 2) + ks * 2);
                mma_f16(acc[2 * np],     a, b);
                mma_f16(acc[2 * np + 1], a, b + 2);
            }
        }
        __syncthreads();
    }

    // Phase 2: h2 tile (bias+relu, fp16) -> SMEM H; load W3.
    const int rowl = warp * 16 + g;
#pragma unroll
    for (int nt = 0; nt < NT; nt++) {
        int col = nt * 8 + 2 * cq;
        float v0 = acc[nt][0] + bias2[col], v1 = acc[nt][1] + bias2[col + 1];
        float v2 = acc[nt][2] + bias2[col], v3 = acc[nt][3] + bias2[col + 1];
        v0 = fmaxf(v0, 0.0f); v1 = fmaxf(v1, 0.0f);
        v2 = fmaxf(v2, 0.0f); v3 = fmaxf(v3, 0.0f);
        __half2 h01 = __floats2half2_rn(v0, v1);
        __half2 h23 = __floats2half2_rn(v2, v3);
        *(__half2*)(H + rowl * RS2 + col)       = h01;
        *(__half2*)(H + (rowl + 8) * RS2 + col) = h23;
    }
    for (int idx = tid; idx < 80 * 16; idx += 256) {   // 16 x 8-half chunks per row
        int j = idx >> 4, part = idx & 15;
        *(uint4*)(W3 + j * RS2 + part * 8) = *(const uint4*)(Wh3 + (size_t)j * 128 + part * 8);
    }
    __syncthreads();

    // Phase 3: t = H @ W3^T  (K=128, N=80), k-order identical to old gemm3.
    constexpr int NT2 = 10, NP2 = 5;
    float acc2[NT2][4];
#pragma unroll
    for (int nt = 0; nt < NT2; nt++)
#pragma unroll
        for (int i = 0; i < 4; i++) acc2[nt][i] = 0.0f;
    const unsigned hBase  = (unsigned)__cvta_generic_to_shared(H);
    const unsigned w3Base = (unsigned)__cvta_generic_to_shared(W3);
    const unsigned aoff2 =
        (unsigned)(((warp * 16 + ((lane >> 3) & 1) * 8 + lr) * RS2 + ((lane >> 4) << 3)) * 2);
    const unsigned boff2 =
        (unsigned)(((((lane >> 4) << 3) + lr) * RS2 + (((lane >> 3) & 1) << 3)) * 2);
#pragma unroll
    for (int ks = 0; ks < 128; ks += 16) {
        unsigned a[4];
        ldsm_x4(a, hBase + aoff2 + ks * 2);
#pragma unroll
        for (int np = 0; np < NP2; np++) {
            unsigned b[4];
            ldsm_x4(b, w3Base + boff2 + (unsigned)(np * 16 * RS2 * 2) + ks * 2);
            mma_f16(acc2[2 * np],     a, b);
            mma_f16(acc2[2 * np + 1], a, b + 2);
        }
    }

    // Phase 4: split epilogue — cols 0..39 fp16 t40h, cols 40..79 fp32 troot.
    const int row0 = rowBase + rowl;
#pragma unroll
    for (int nt = 0; nt < NT2; nt++) {
        int col = nt * 8 + 2 * cq;
        float v0 = acc2[nt][0], v1 = acc2[nt][1], v2 = acc2[nt][2], v3 = acc2[nt][3];
        if (col < 40) {
            if (row0 < Nrows) {
                __half2 h = __floats2half2_rn(v0, v1);
                *(unsigned*)(C40 + (size_t)row0 * 40 + col) = *(unsigned*)&h;
            }
            if (row0 + 8 < Nrows) {
                __half2 h = __floats2half2_rn(v2, v3);
                *(unsigned*)(C40 + (size_t)(row0 + 8) * 40 + col) = *(unsigned*)&h;
            }
        } else {
            int rc = col - 40;
            if (row0 < Nrows) {
                float* p = Croot + (size_t)row0 * 40 + rc;
                p[0] = v0; p[1] = v1;
            }
            if (row0 + 8 < Nrows) {
                float* p = Croot + (size_t)(row0 + 8) * 40 + rc;
                p[0] = v2; p[1] = v3;
            }
        }
    }
}

// ---------------- fused final: TWO nodes per warp (half-warp each) --------------
// mean-agg of t40h (fp16) + troot + bias + log_softmax; 10 of 16 lanes gather.
__global__ void final_kernel(const float* __restrict__ b3,
                             float* __restrict__ out) {
    int gw   = (blockIdx.x * blockDim.x + threadIdx.x) >> 5;
    int lane = threadIdx.x & 31;
    int hw   = lane >> 4;
    int sl   = lane & 15;
    int node = gw * 2 + hw;
    if (node >= N_NODES) return;     // N even: whole warp exits together
    const bool act = (sl < 10);
    const int col = 4 * sl;
    int beg = g_off[node], end = g_off[node + 1];
    int deg = end - beg;
    int mx  = max(deg, __shfl_xor_sync(0xFFFFFFFFu, deg, 16));
    float a0 = 0.f, a1 = 0.f, a2 = 0.f, a3 = 0.f;
    for (int c = 0; c < mx; c += 16) {
        int m = deg - c; if (m > 16) m = 16;
        int sidx = (sl < m) ? __ldg(g_src_sorted + beg + c + sl) : 0;
        int mm = mx - c; if (mm > 16) mm = 16;
        for (int i = 0; i < mm; i += 4) {
            int s0 = __shfl_sync(0xFFFFFFFFu, sidx, i,     16);
            int s1 = __shfl_sync(0xFFFFFFFFu, sidx, i + 1, 16);
            int s2 = __shfl_sync(0xFFFFFFFFu, sidx, i + 2, 16);
            int s3 = __shfl_sync(0xFFFFFFFFu, sidx, i + 3, 16);
            float2 f;
            if (act && i < m) {
                uint2 v = *(const uint2*)(g_t40h + (size_t)s0 * 40 + col);
                f = __half22float2(*(__half2*)&v.x); a0 += f.x; a1 += f.y;
                f = __half22float2(*(__half2*)&v.y); a2 += f.x; a3 += f.y;
            }
            if (act && i + 1 < m) {
                uint2 v = *(const uint2*)(g_t40h + (size_t)s1 * 40 + col);
                f = __half22float2(*(__half2*)&v.x); a0 += f.x; a1 += f.y;
                f = __half22float2(*(__half2*)&v.y); a2 += f.x; a3 += f.y;
            }
            if (act && i + 2 < m) {
                uint2 v = *(const uint2*)(g_t40h + (size_t)s2 * 40 + col);
                f = __half22float2(*(__half2*)&v.x); a0 += f.x; a1 += f.y;
                f = __half22float2(*(__half2*)&v.y); a2 += f.x; a3 += f.y;
            }
            if (act && i + 3 < m) {
                uint2 v = *(const uint2*)(g_t40h + (size_t)s3 * 40 + col);
                f = __half22float2(*(__half2*)&v.x); a0 += f.x; a1 += f.y;
                f = __half22float2(*(__half2*)&v.y); a2 += f.x; a3 += f.y;
            }
        }
    }
    float v0 = -INFINITY, v1 = -INFINITY, v2 = -INFINITY, v3 = -INFINITY;
    if (act) {
        float inv = g_inv_deg[node];
        float4 rt = *(const float4*)(g_troot + (size_t)node * 40 + col);
        float4 bb = *(const float4*)(b3 + col);
        v0 = a0 * inv + rt.x + bb.x;
        v1 = a1 * inv + rt.y + bb.y;
        v2 = a2 * inv + rt.z + bb.z;
        v3 = a3 * inv + rt.w + bb.w;
    }
    float m = fmaxf(fmaxf(v0, v1), fmaxf(v2, v3));
#pragma unroll
    for (int s = 8; s; s >>= 1) m = fmaxf(m, __shfl_xor_sync(0xFFFFFFFFu, m, s));
    float e = 0.0f;
    if (act)
        e = __expf(v0 - m) + __expf(v1 - m) + __expf(v2 - m) + __expf(v3 - m);
#pragma unroll
    for (int s = 8; s; s >>= 1) e += __shfl_xor_sync(0xFFFFFFFFu, e, s);
    float lse = m + logf(e);
    if (act) {
        float4 o;
        o.x = v0 - lse; o.y = v1 - lse; o.z = v2 - lse; o.w = v3 - lse;
        *(float4*)(out + (size_t)node * 40 + col) = o;
    }
}

// ---------------- launch ----------------
extern "C" void kernel_launch(void* const* d_in, const int* in_sizes, int n_in,
                              void* d_out, int out_size) {
    const float* x    = (const float*)d_in[0];
    const int*   ei   = (const int*)d_in[1];   // [2, E] int32: row0=src, row1=dst
    const float* w1_l = (const float*)d_in[2];
    const float* w1_r = (const float*)d_in[3];
    const float* b1   = (const float*)d_in[4];
    const float* w2_l = (const float*)d_in[5];
    const float* w2_r = (const float*)d_in[6];
    const float* b2   = (const float*)d_in[7];
    const float* w3_l = (const float*)d_in[8];
    const float* w3_r = (const float*)d_in[9];
    const float* b3   = (const float*)d_in[10];
    float* out = (float*)d_out;

    const int* src = ei;
    const int* dst = ei + N_EDGES;

    __half *xh, *agg, *h1, *wh1, *wh2, *wh3, *t40h;
    float *troot;
    cudaGetSymbolAddress((void**)&xh,    g_xh);
    cudaGetSymbolAddress((void**)&agg,   g_agg);
    cudaGetSymbolAddress((void**)&h1,    g_h1);
    cudaGetSymbolAddress((void**)&t40h,  g_t40h);
    cudaGetSymbolAddress((void**)&troot, g_troot);
    cudaGetSymbolAddress((void**)&wh1,   g_wh1);
    cudaGetSymbolAddress((void**)&wh2,   g_wh2);
    cudaGetSymbolAddress((void**)&wh3,   g_wh3);

    const int TB = 256;
    const int convThreads = (N_NODES * 64) / 4;                 // 1.6M
    const int histBlocks  = (convThreads + TB - 1) / TB;
    const int warpBlocks  = (N_NODES * 32 + TB - 1) / TB;
    const int pairBlocks  = (N_NODES / 2 * 32 + TB - 1) / TB;
    const int gemmBlocks  = (N_NODES + 127) / 128;
    const int g23Smem     = GEMM23_SMEM_HALVES * 2;             // 56576 B

    cudaFuncSetAttribute(gemm23_kernel,
                         cudaFuncAttributeMaxDynamicSharedMemorySize, g23Smem);

    // CSR build + x->fp16 + weight prep (g_count re-zeroed inside scanC)
    hist_conv_kernel<<<histBlocks, TB>>>(dst, x, w1_l, w1_r, w2_l, w2_r, w3_l, w3_r);
    scanA_kernel<<<SCAN_NB, 1024>>>();
    scanC_kernel<<<SCAN_NB, 1024>>>();
    scatter_kernel<<<(N_EDGES + TB - 1) / TB, TB>>>(src, dst);
    sort_kernel<<<warpBlocks, TB>>>();

    // Layer 1
    aggregate64_kernel<<<pairBlocks, TB>>>(xh, agg);
    gemm1_kernel<<<gemmBlocks, TB>>>(agg, 64, xh, 64, wh1, b1, h1, N_NODES);

    // Layer 2 + 3 fused (h2 never leaves SMEM)
    aggregate128_kernel<<<warpBlocks, TB>>>(h1, agg);
    gemm23_kernel<<<gemmBlocks, TB, g23Smem>>>(agg, h1, wh2, wh3, b2,
                                               t40h, troot, N_NODES);

    // fused: mean-agg of t40h + troot + b3 + log_softmax (2 nodes/warp)
    final_kernel<<<pairBlocks, TB>>>(b3, out);
}